// round 1
// baseline (speedup 1.0000x reference)
#include <cuda_runtime.h>
#include <math.h>

// Problem constants
#define NQ   8192    // query rows
#define MKV  8192    // key/value rows
#define DIM  1024    // in/out feature dim for all projections

// ---------------------------------------------------------------------------
// Scratch (static __device__ globals — no allocation at runtime)
// ---------------------------------------------------------------------------
__device__ float g_Q[(size_t)NQ * DIM];           // 32 MB
__device__ float g_K[(size_t)MKV * DIM];          // 32 MB
__device__ float g_V[(size_t)MKV * DIM];          // 32 MB
__device__ float g_S[(size_t)NQ * MKV];           // 256 MB (scores / probs)

// ---------------------------------------------------------------------------
// Generic 128x128x8 register-blocked SGEMM.
//   C[m,n] = alpha * sum_k A[m,k] * B(k,n)  (+ bias[n])
//   TRANSB = true : B is stored as B[n,k] (row-major, ldb = K)   -> C = A @ B^T
//   TRANSB = false: B is stored as B[k,n] (row-major, ldb = Ncols)
// All dims must be multiples of 128 (M, Ncols) and 8 (K). True here.
// 256 threads (16x16), each computes an 8x8 micro-tile.
// ---------------------------------------------------------------------------
template <bool TRANSB, bool BIAS>
__global__ __launch_bounds__(256, 2)
void sgemm128(const float* __restrict__ A,
              const float* __restrict__ B,
              const float* __restrict__ bias,
              float* __restrict__ C,
              int M, int Ncols, int K, float alpha)
{
    __shared__ float As[8][128];
    __shared__ float Bs[8][128];

    const int tx  = threadIdx.x;           // 0..15
    const int ty  = threadIdx.y;           // 0..15
    const int tid = ty * 16 + tx;          // 0..255

    const int rowBase = blockIdx.y * 128;
    const int colBase = blockIdx.x * 128;

    // A-load mapping: 128 rows x 8 cols via 256 float4 loads
    const int aRow  = tid >> 1;            // 0..127
    const int aCol4 = (tid & 1) * 4;       // 0 or 4

    // B-load mapping for NN layout: 8 rows (k) x 128 cols
    const int bRowNN  = tid >> 5;          // 0..7
    const int bColNN  = (tid & 31) * 4;    // 0..124

    float acc[8][8];
#pragma unroll
    for (int i = 0; i < 8; i++)
#pragma unroll
        for (int j = 0; j < 8; j++)
            acc[i][j] = 0.0f;

    const size_t ldA = (size_t)K;

    for (int k0 = 0; k0 < K; k0 += 8) {
        // ---- load A tile (transposed into As[k][row]) ----
        {
            const float4 av = *reinterpret_cast<const float4*>(
                &A[(size_t)(rowBase + aRow) * ldA + (k0 + aCol4)]);
            As[aCol4 + 0][aRow] = av.x;
            As[aCol4 + 1][aRow] = av.y;
            As[aCol4 + 2][aRow] = av.z;
            As[aCol4 + 3][aRow] = av.w;
        }
        // ---- load B tile ----
        if (TRANSB) {
            // B[n,k], ldb = K. Tile: 128 n-rows x 8 k-cols, store Bs[k][n]
            const float4 bv = *reinterpret_cast<const float4*>(
                &B[(size_t)(colBase + aRow) * (size_t)K + (k0 + aCol4)]);
            Bs[aCol4 + 0][aRow] = bv.x;
            Bs[aCol4 + 1][aRow] = bv.y;
            Bs[aCol4 + 2][aRow] = bv.z;
            Bs[aCol4 + 3][aRow] = bv.w;
        } else {
            // B[k,n], ldb = Ncols. Tile: 8 k-rows x 128 n-cols (coalesced)
            const float4 bv = *reinterpret_cast<const float4*>(
                &B[(size_t)(k0 + bRowNN) * (size_t)Ncols + (colBase + bColNN)]);
            *reinterpret_cast<float4*>(&Bs[bRowNN][bColNN]) = bv;
        }
        __syncthreads();

        // ---- compute ----
#pragma unroll
        for (int kk = 0; kk < 8; kk++) {
            float ra[8], rb[8];
#pragma unroll
            for (int i = 0; i < 8; i++) ra[i] = As[kk][ty * 8 + i];
#pragma unroll
            for (int j = 0; j < 8; j++) rb[j] = Bs[kk][tx * 8 + j];
#pragma unroll
            for (int i = 0; i < 8; i++)
#pragma unroll
                for (int j = 0; j < 8; j++)
                    acc[i][j] = fmaf(ra[i], rb[j], acc[i][j]);
        }
        __syncthreads();
    }

    // ---- epilogue ----
    float bv[8];
#pragma unroll
    for (int j = 0; j < 8; j++)
        bv[j] = BIAS ? bias[colBase + tx * 8 + j] : 0.0f;

#pragma unroll
    for (int i = 0; i < 8; i++) {
        const size_t rowOff = (size_t)(rowBase + ty * 8 + i) * (size_t)Ncols
                              + colBase + tx * 8;
        float4 o0, o1;
        o0.x = alpha * acc[i][0] + bv[0];
        o0.y = alpha * acc[i][1] + bv[1];
        o0.z = alpha * acc[i][2] + bv[2];
        o0.w = alpha * acc[i][3] + bv[3];
        o1.x = alpha * acc[i][4] + bv[4];
        o1.y = alpha * acc[i][5] + bv[5];
        o1.z = alpha * acc[i][6] + bv[6];
        o1.w = alpha * acc[i][7] + bv[7];
        *reinterpret_cast<float4*>(&C[rowOff + 0]) = o0;
        *reinterpret_cast<float4*>(&C[rowOff + 4]) = o1;
    }
}

// ---------------------------------------------------------------------------
// Row softmax over S (row length MKV = 8192), in place.
// One block of 256 threads per row; 32 elements/thread held in registers.
// Single global read + single global write of S.
// ---------------------------------------------------------------------------
__global__ __launch_bounds__(256)
void softmax_rows(float* __restrict__ S)
{
    __shared__ float red[256];

    const int row = blockIdx.x;
    const int t   = threadIdx.x;
    float4* p = reinterpret_cast<float4*>(S + (size_t)row * MKV);

    float4 v[8];
    float mx = -INFINITY;
#pragma unroll
    for (int i = 0; i < 8; i++) {
        v[i] = p[t + i * 256];
        mx = fmaxf(mx, fmaxf(fmaxf(v[i].x, v[i].y), fmaxf(v[i].z, v[i].w)));
    }

    // block max reduce
    red[t] = mx;
    __syncthreads();
    for (int s = 128; s > 0; s >>= 1) {
        if (t < s) red[t] = fmaxf(red[t], red[t + s]);
        __syncthreads();
    }
    mx = red[0];
    __syncthreads();

    float sum = 0.0f;
#pragma unroll
    for (int i = 0; i < 8; i++) {
        v[i].x = __expf(v[i].x - mx);
        v[i].y = __expf(v[i].y - mx);
        v[i].z = __expf(v[i].z - mx);
        v[i].w = __expf(v[i].w - mx);
        sum += v[i].x + v[i].y + v[i].z + v[i].w;
    }

    // block sum reduce
    red[t] = sum;
    __syncthreads();
    for (int s = 128; s > 0; s >>= 1) {
        if (t < s) red[t] += red[t + s];
        __syncthreads();
    }
    const float inv = 1.0f / red[0];

#pragma unroll
    for (int i = 0; i < 8; i++) {
        v[i].x *= inv; v[i].y *= inv; v[i].z *= inv; v[i].w *= inv;
        p[t + i * 256] = v[i];
    }
}

// ---------------------------------------------------------------------------
// Launch
// ---------------------------------------------------------------------------
extern "C" void kernel_launch(void* const* d_in, const int* in_sizes, int n_in,
                              void* d_out, int out_size)
{
    const float* query = (const float*)d_in[0];   // (8192, 1024)
    const float* key   = (const float*)d_in[1];   // (8192, 1024)
    const float* value = (const float*)d_in[2];   // (8192, 1024)
    const float* Wq    = (const float*)d_in[3];   // (1024, 1024)
    const float* bq    = (const float*)d_in[4];   // (1024,)
    const float* Wk    = (const float*)d_in[5];
    const float* bk    = (const float*)d_in[6];
    const float* Wv    = (const float*)d_in[7];
    const float* bv    = (const float*)d_in[8];
    float* out = (float*)d_out;                   // (8192, 1024)

    float *Qp, *Kp, *Vp, *Sp;
    cudaGetSymbolAddress((void**)&Qp, g_Q);
    cudaGetSymbolAddress((void**)&Kp, g_K);
    cudaGetSymbolAddress((void**)&Vp, g_V);
    cudaGetSymbolAddress((void**)&Sp, g_S);

    dim3 blk(16, 16);

    // Projections: X @ W^T + b   (M=8192, N=1024, K=1024, B transposed)
    {
        dim3 grid(DIM / 128, NQ / 128);
        sgemm128<true, true><<<grid, blk>>>(query, Wq, bq, Qp, NQ, DIM, DIM, 1.0f);
        sgemm128<true, true><<<grid, blk>>>(key,   Wk, bk, Kp, MKV, DIM, DIM, 1.0f);
        sgemm128<true, true><<<grid, blk>>>(value, Wv, bv, Vp, MKV, DIM, DIM, 1.0f);
    }

    // S = Q @ K^T / sqrt(1024)   (M=8192, N=8192, K=1024, B transposed)
    {
        dim3 grid(MKV / 128, NQ / 128);
        sgemm128<true, false><<<grid, blk>>>(Qp, Kp, nullptr, Sp,
                                             NQ, MKV, DIM, 1.0f / 32.0f);
    }

    // Row softmax in place
    softmax_rows<<<NQ, 256>>>(Sp);

    // out = P @ V   (M=8192, N=1024, K=8192, B not transposed)
    {
        dim3 grid(DIM / 128, NQ / 128);
        sgemm128<false, false><<<grid, blk>>>(Sp, Vp, nullptr, out,
                                              NQ, DIM, MKV, 1.0f);
    }
}

// round 2
// speedup vs baseline: 3.2455x; 3.2455x over previous
#include <cuda_runtime.h>
#include <math.h>
#include <stdint.h>

// Problem constants
#define NQ   8192
#define MKV  8192
#define DIM  1024

// ---------------------------------------------------------------------------
// Scratch (__device__ globals — no runtime allocation)
// ---------------------------------------------------------------------------
__device__ float g_Q[(size_t)NQ * DIM];            // 32 MB (tf32-rounded)
__device__ float g_K[(size_t)MKV * DIM];           // 32 MB (tf32-rounded)
__device__ float g_Vt[(size_t)DIM * MKV];          // 32 MB, TRANSPOSED [d][m], tf32-rounded
__device__ float g_S[(size_t)NQ * MKV];            // 256 MB scores/probs

// ---------------------------------------------------------------------------
// Helpers
// ---------------------------------------------------------------------------
__device__ __forceinline__ float rnd_tf32(float x) {
    uint32_t u;
    asm("cvt.rna.tf32.f32 %0, %1;" : "=r"(u) : "f"(x));
    return __uint_as_float(u);
}
__device__ __forceinline__ uint32_t cvt_tf32(float x) {
    uint32_t u;
    asm("cvt.rna.tf32.f32 %0, %1;" : "=r"(u) : "f"(x));
    return u;
}

#define CP_ASYNC16(dst, src) \
    asm volatile("cp.async.cg.shared.global [%0], [%1], 16;" :: "r"(dst), "l"(src))
#define CP_COMMIT() asm volatile("cp.async.commit_group;")
#define CP_WAIT(n)  asm volatile("cp.async.wait_group %0;" :: "n"(n))

#define MMA_TF32(d0,d1,d2,d3,a0,a1,a2,a3,b0,b1)                                   \
    asm volatile("mma.sync.aligned.m16n8k8.row.col.f32.tf32.tf32.f32 "            \
                 "{%0,%1,%2,%3},{%4,%5,%6,%7},{%8,%9},{%0,%1,%2,%3};"             \
                 : "+f"(d0), "+f"(d1), "+f"(d2), "+f"(d3)                         \
                 : "r"(a0), "r"(a1), "r"(a2), "r"(a3), "r"(b0), "r"(b1))

// ---------------------------------------------------------------------------
// Tensor-core TF32 GEMM: C[m,n] = alpha * A[m,:] . B[n,:]  (+ bias[n])
// A row-major (lda), B row-major per-n (ldb)  -> C = A @ B^T, C row-major (ldc)
// Tiles: BM=128, BN=128, BK=32. 256 threads, warp grid 2x4, 64x32 per warp.
// CVT   : round fragments to tf32 at load (for raw-fp32 inputs)
// BIASF : add bias[n]
// RND   : round outputs to tf32
// ---------------------------------------------------------------------------
#define BMT 128
#define BNT 128
#define BKT 32
#define KPAD 36   // pad so fragment LDS bank = lane (conflict-free); rows stay 16B-aligned

__device__ __forceinline__ void load_tile_cp(uint32_t sbase_bytes,
                                             const float* __restrict__ g,
                                             int ld, int rowB, int k0, int tid)
{
    const int r = tid >> 3;        // 0..31
    const int c = tid & 7;         // 0..7  (16B chunk)
#pragma unroll
    for (int i = 0; i < 4; i++) {
        const int row = r + 32 * i;
        const float* src = g + (size_t)(rowB + row) * ld + k0 + c * 4;
        CP_ASYNC16(sbase_bytes + (uint32_t)(row * KPAD + c * 4) * 4u, src);
    }
}

template <bool CVT, bool BIASF, bool RND>
__global__ __launch_bounds__(256, 2)
void gemm_tc(const float* __restrict__ A, const float* __restrict__ B,
             const float* __restrict__ bias, float* __restrict__ C,
             int M, int N, int K, int lda, int ldb, int ldc, float alpha)
{
    extern __shared__ float sm[];
    float* AsBase = sm;                          // [2][BMT][KPAD]
    float* BsBase = sm + 2 * BMT * KPAD;         // [2][BNT][KPAD]

    const int tid  = threadIdx.x;
    const int lane = tid & 31;
    const int warp = tid >> 5;
    const int wm   = warp >> 2;                  // 0..1
    const int wn   = warp & 3;                   // 0..3
    const int g    = lane >> 2;                  // groupID 0..7
    const int t4   = lane & 3;                   // 0..3

    const int rowBase = blockIdx.y * BMT;
    const int colBase = blockIdx.x * BNT;

    uint32_t sA = (uint32_t)__cvta_generic_to_shared(AsBase);
    uint32_t sB = (uint32_t)__cvta_generic_to_shared(BsBase);
    const uint32_t TILE_B = (uint32_t)BMT * KPAD * 4u;   // bytes per buffer (A and B same shape)

    float acc[4][4][4];
#pragma unroll
    for (int mi = 0; mi < 4; mi++)
#pragma unroll
        for (int ni = 0; ni < 4; ni++)
#pragma unroll
            for (int r = 0; r < 4; r++) acc[mi][ni][r] = 0.0f;

    // Prologue: stage k-block 0 into buffer 0
    load_tile_cp(sA, A, lda, rowBase, 0, tid);
    load_tile_cp(sB, B, ldb, colBase, 0, tid);
    CP_COMMIT();

    const int KT = K / BKT;
    for (int kt = 0; kt < KT; kt++) {
        const int buf = kt & 1;
        if (kt + 1 < KT) {
            const int nbuf = buf ^ 1;
            load_tile_cp(sA + nbuf * TILE_B, A, lda, rowBase, (kt + 1) * BKT, tid);
            load_tile_cp(sB + nbuf * TILE_B, B, ldb, colBase, (kt + 1) * BKT, tid);
            CP_COMMIT();
            CP_WAIT(1);
        } else {
            CP_WAIT(0);
        }
        __syncthreads();

        const float* As = AsBase + buf * BMT * KPAD + (wm * 64 + g) * KPAD;
        const float* Bs = BsBase + buf * BNT * KPAD + (wn * 32 + g) * KPAD;

#pragma unroll
        for (int kk = 0; kk < 4; kk++) {
            uint32_t af[4][4], bf[4][2];
            const int ko = kk * 8 + t4;
#pragma unroll
            for (int mi = 0; mi < 4; mi++) {
                const float* p = As + mi * 16 * KPAD + ko;
                float x0 = p[0];
                float x1 = p[8 * KPAD];
                float x2 = p[4];
                float x3 = p[8 * KPAD + 4];
                if (CVT) {
                    af[mi][0] = cvt_tf32(x0); af[mi][1] = cvt_tf32(x1);
                    af[mi][2] = cvt_tf32(x2); af[mi][3] = cvt_tf32(x3);
                } else {
                    af[mi][0] = __float_as_uint(x0); af[mi][1] = __float_as_uint(x1);
                    af[mi][2] = __float_as_uint(x2); af[mi][3] = __float_as_uint(x3);
                }
            }
#pragma unroll
            for (int ni = 0; ni < 4; ni++) {
                const float* p = Bs + ni * 8 * KPAD + ko;
                float y0 = p[0];
                float y1 = p[4];
                if (CVT) {
                    bf[ni][0] = cvt_tf32(y0); bf[ni][1] = cvt_tf32(y1);
                } else {
                    bf[ni][0] = __float_as_uint(y0); bf[ni][1] = __float_as_uint(y1);
                }
            }
#pragma unroll
            for (int mi = 0; mi < 4; mi++)
#pragma unroll
                for (int ni = 0; ni < 4; ni++)
                    MMA_TF32(acc[mi][ni][0], acc[mi][ni][1], acc[mi][ni][2], acc[mi][ni][3],
                             af[mi][0], af[mi][1], af[mi][2], af[mi][3],
                             bf[ni][0], bf[ni][1]);
        }
        __syncthreads();
    }

    // Epilogue
#pragma unroll
    for (int mi = 0; mi < 4; mi++) {
#pragma unroll
        for (int ni = 0; ni < 4; ni++) {
            const int r0 = rowBase + wm * 64 + mi * 16 + g;
            const int c0 = colBase + wn * 32 + ni * 8 + 2 * t4;
            float bv0 = 0.0f, bv1 = 0.0f;
            if (BIASF) { bv0 = bias[c0]; bv1 = bias[c0 + 1]; }
            float v0 = alpha * acc[mi][ni][0] + bv0;
            float v1 = alpha * acc[mi][ni][1] + bv1;
            float v2 = alpha * acc[mi][ni][2] + bv0;
            float v3 = alpha * acc[mi][ni][3] + bv1;
            if (RND) { v0 = rnd_tf32(v0); v1 = rnd_tf32(v1);
                       v2 = rnd_tf32(v2); v3 = rnd_tf32(v3); }
            float2 o01 = make_float2(v0, v1);
            float2 o23 = make_float2(v2, v3);
            *reinterpret_cast<float2*>(&C[(size_t)r0 * ldc + c0])       = o01;
            *reinterpret_cast<float2*>(&C[(size_t)(r0 + 8) * ldc + c0]) = o23;
        }
    }
}

// ---------------------------------------------------------------------------
// fp32 FFMA SGEMM (kept for the V projection — precision-critical term).
// C = A @ B^T + bias (TRANSB fixed true here). TRANSC: write C transposed
// [n][m] with ld = M (produces g_Vt). RND: round outputs to tf32.
// ---------------------------------------------------------------------------
template <bool TRANSC, bool RND>
__global__ __launch_bounds__(256, 2)
void sgemm128(const float* __restrict__ A, const float* __restrict__ B,
              const float* __restrict__ bias, float* __restrict__ C,
              int M, int Ncols, int K, float alpha)
{
    __shared__ float As[8][128];
    __shared__ float Bs[8][128];

    const int tx = threadIdx.x, ty = threadIdx.y;
    const int tid = ty * 16 + tx;
    const int rowBase = blockIdx.y * 128;
    const int colBase = blockIdx.x * 128;
    const int aRow = tid >> 1;
    const int aCol4 = (tid & 1) * 4;

    float acc[8][8];
#pragma unroll
    for (int i = 0; i < 8; i++)
#pragma unroll
        for (int j = 0; j < 8; j++) acc[i][j] = 0.0f;

    for (int k0 = 0; k0 < K; k0 += 8) {
        {
            const float4 av = *reinterpret_cast<const float4*>(
                &A[(size_t)(rowBase + aRow) * K + (k0 + aCol4)]);
            As[aCol4 + 0][aRow] = av.x; As[aCol4 + 1][aRow] = av.y;
            As[aCol4 + 2][aRow] = av.z; As[aCol4 + 3][aRow] = av.w;
        }
        {
            const float4 bv = *reinterpret_cast<const float4*>(
                &B[(size_t)(colBase + aRow) * K + (k0 + aCol4)]);
            Bs[aCol4 + 0][aRow] = bv.x; Bs[aCol4 + 1][aRow] = bv.y;
            Bs[aCol4 + 2][aRow] = bv.z; Bs[aCol4 + 3][aRow] = bv.w;
        }
        __syncthreads();
#pragma unroll
        for (int kk = 0; kk < 8; kk++) {
            float ra[8], rb[8];
#pragma unroll
            for (int i = 0; i < 8; i++) ra[i] = As[kk][ty * 8 + i];
#pragma unroll
            for (int j = 0; j < 8; j++) rb[j] = Bs[kk][tx * 8 + j];
#pragma unroll
            for (int i = 0; i < 8; i++)
#pragma unroll
                for (int j = 0; j < 8; j++)
                    acc[i][j] = fmaf(ra[i], rb[j], acc[i][j]);
        }
        __syncthreads();
    }

    float bvv[8];
#pragma unroll
    for (int j = 0; j < 8; j++) bvv[j] = bias[colBase + tx * 8 + j];

    if (TRANSC) {
        // C^T layout [n][m], ld = M
#pragma unroll
        for (int j = 0; j < 8; j++) {
            float v[8];
#pragma unroll
            for (int i = 0; i < 8; i++) {
                float x = alpha * acc[i][j] + bvv[j];
                v[i] = RND ? rnd_tf32(x) : x;
            }
            const size_t off = (size_t)(colBase + tx * 8 + j) * (size_t)M
                               + rowBase + ty * 8;
            *reinterpret_cast<float4*>(&C[off + 0]) = make_float4(v[0], v[1], v[2], v[3]);
            *reinterpret_cast<float4*>(&C[off + 4]) = make_float4(v[4], v[5], v[6], v[7]);
        }
    } else {
#pragma unroll
        for (int i = 0; i < 8; i++) {
            const size_t off = (size_t)(rowBase + ty * 8 + i) * (size_t)Ncols
                               + colBase + tx * 8;
            float v[8];
#pragma unroll
            for (int j = 0; j < 8; j++) {
                float x = alpha * acc[i][j] + bvv[j];
                v[j] = RND ? rnd_tf32(x) : x;
            }
            *reinterpret_cast<float4*>(&C[off + 0]) = make_float4(v[0], v[1], v[2], v[3]);
            *reinterpret_cast<float4*>(&C[off + 4]) = make_float4(v[4], v[5], v[6], v[7]);
        }
    }
}

// ---------------------------------------------------------------------------
// Row softmax over S (8192 per row), in place; outputs rounded to tf32.
// ---------------------------------------------------------------------------
__global__ __launch_bounds__(256)
void softmax_rows(float* __restrict__ S)
{
    __shared__ float red[256];
    const int row = blockIdx.x;
    const int t = threadIdx.x;
    float4* p = reinterpret_cast<float4*>(S + (size_t)row * MKV);

    float4 v[8];
    float mx = -INFINITY;
#pragma unroll
    for (int i = 0; i < 8; i++) {
        v[i] = p[t + i * 256];
        mx = fmaxf(mx, fmaxf(fmaxf(v[i].x, v[i].y), fmaxf(v[i].z, v[i].w)));
    }
    red[t] = mx; __syncthreads();
    for (int s = 128; s > 0; s >>= 1) {
        if (t < s) red[t] = fmaxf(red[t], red[t + s]);
        __syncthreads();
    }
    mx = red[0]; __syncthreads();

    float sum = 0.0f;
#pragma unroll
    for (int i = 0; i < 8; i++) {
        v[i].x = __expf(v[i].x - mx); v[i].y = __expf(v[i].y - mx);
        v[i].z = __expf(v[i].z - mx); v[i].w = __expf(v[i].w - mx);
        sum += v[i].x + v[i].y + v[i].z + v[i].w;
    }
    red[t] = sum; __syncthreads();
    for (int s = 128; s > 0; s >>= 1) {
        if (t < s) red[t] += red[t + s];
        __syncthreads();
    }
    const float inv = 1.0f / red[0];

#pragma unroll
    for (int i = 0; i < 8; i++) {
        v[i].x = rnd_tf32(v[i].x * inv); v[i].y = rnd_tf32(v[i].y * inv);
        v[i].z = rnd_tf32(v[i].z * inv); v[i].w = rnd_tf32(v[i].w * inv);
        p[t + i * 256] = v[i];
    }
}

// ---------------------------------------------------------------------------
// Launch
// ---------------------------------------------------------------------------
extern "C" void kernel_launch(void* const* d_in, const int* in_sizes, int n_in,
                              void* d_out, int out_size)
{
    const float* query = (const float*)d_in[0];
    const float* key   = (const float*)d_in[1];
    const float* value = (const float*)d_in[2];
    const float* Wq    = (const float*)d_in[3];
    const float* bq    = (const float*)d_in[4];
    const float* Wk    = (const float*)d_in[5];
    const float* bk    = (const float*)d_in[6];
    const float* Wv    = (const float*)d_in[7];
    const float* bv    = (const float*)d_in[8];
    float* out = (float*)d_out;

    float *Qp, *Kp, *Vtp, *Sp;
    cudaGetSymbolAddress((void**)&Qp, g_Q);
    cudaGetSymbolAddress((void**)&Kp, g_K);
    cudaGetSymbolAddress((void**)&Vtp, g_Vt);
    cudaGetSymbolAddress((void**)&Sp, g_S);

    const int SMEMB = 2 * (BMT + BNT) * KPAD * 4;   // 73728 bytes

    cudaFuncSetAttribute(gemm_tc<true, true, true>,
                         cudaFuncAttributeMaxDynamicSharedMemorySize, SMEMB);
    cudaFuncSetAttribute(gemm_tc<false, false, false>,
                         cudaFuncAttributeMaxDynamicSharedMemorySize, SMEMB);

    // Q/K projections on tensor cores (tf32, cvt.rna on fragments), tf32-rounded out
    {
        dim3 grid(DIM / BNT, NQ / BMT);
        gemm_tc<true, true, true><<<grid, 256, SMEMB>>>(
            query, Wq, bq, Qp, NQ, DIM, DIM, DIM, DIM, DIM, 1.0f);
        gemm_tc<true, true, true><<<grid, 256, SMEMB>>>(
            key, Wk, bk, Kp, MKV, DIM, DIM, DIM, DIM, DIM, 1.0f);
    }
    // V projection in fp32 FFMA (precision-critical), write TRANSPOSED + tf32-rounded
    {
        dim3 grid(DIM / 128, MKV / 128), blk(16, 16);
        sgemm128<true, true><<<grid, blk>>>(value, Wv, bv, Vtp, MKV, DIM, DIM, 1.0f);
    }
    // S = Q K^T / 32  (tensor core, pre-rounded inputs)
    {
        dim3 grid(MKV / BNT, NQ / BMT);
        gemm_tc<false, false, false><<<grid, 256, SMEMB>>>(
            Qp, Kp, nullptr, Sp, NQ, MKV, DIM, DIM, DIM, MKV, 1.0f / 32.0f);
    }
    // softmax (rounds P to tf32)
    softmax_rows<<<NQ, 256>>>(Sp);
    // out = P @ V  (tensor core; B = Vt so it is already "col-major")
    {
        dim3 grid(DIM / BNT, NQ / BMT);
        gemm_tc<false, false, false><<<grid, 256, SMEMB>>>(
            Sp, Vtp, nullptr, out, NQ, DIM, MKV, MKV, MKV, DIM, 1.0f);
    }
}

// round 6
// speedup vs baseline: 8.3189x; 2.5632x over previous
#include <cuda_runtime.h>
#include <cuda_fp16.h>
#include <math.h>
#include <stdint.h>

#define NQ   8192
#define MKV  8192
#define DIM  1024

// ---------------------------------------------------------------------------
// Scratch (__device__ globals)
// ---------------------------------------------------------------------------
__device__ __half g_qh[(size_t)NQ * DIM];           // fp16 copies of inputs
__device__ __half g_kh[(size_t)MKV * DIM];
__device__ __half g_vh[(size_t)MKV * DIM];
__device__ __half g_Wqh[(size_t)DIM * DIM];
__device__ __half g_Wkh[(size_t)DIM * DIM];
__device__ __half g_Wvh[(size_t)DIM * DIM];
__device__ __half g_Qh[(size_t)NQ * DIM];           // projected Q (fp16)
__device__ __half g_Kh[(size_t)MKV * DIM];          // projected K (fp16)
__device__ __half g_Vth[(size_t)DIM * MKV];         // projected V, TRANSPOSED [d][m]
__device__ __half g_Sh[(size_t)NQ * MKV];           // scores / probs (fp16), 128 MB

// ---------------------------------------------------------------------------
// PTX helpers (sm_80-era features only; legal on plain sm_100 target)
// ---------------------------------------------------------------------------
#define CP_ASYNC16(dst, src) \
    asm volatile("cp.async.cg.shared.global [%0], [%1], 16;" :: "r"(dst), "l"(src))
#define CP_COMMIT() asm volatile("cp.async.commit_group;")
#define CP_WAIT(n)  asm volatile("cp.async.wait_group %0;" :: "n"(n))

#define LDSM_X4(r0, r1, r2, r3, addr)                                            \
    asm volatile("ldmatrix.sync.aligned.m8n8.x4.shared.b16 {%0,%1,%2,%3}, [%4];" \
                 : "=r"(r0), "=r"(r1), "=r"(r2), "=r"(r3) : "r"(addr))

#define MMA_F16(d, a, b)                                                          \
    asm volatile("mma.sync.aligned.m16n8k16.row.col.f32.f16.f16.f32 "             \
                 "{%0,%1,%2,%3},{%4,%5,%6,%7},{%8,%9},{%0,%1,%2,%3};"             \
                 : "+f"((d)[0]), "+f"((d)[1]), "+f"((d)[2]), "+f"((d)[3])         \
                 : "r"((a)[0]), "r"((a)[1]), "r"((a)[2]), "r"((a)[3]),            \
                   "r"((b)[0]), "r"((b)[1]))

__device__ __forceinline__ uint32_t SWZ128(uint32_t o) { return o ^ ((o >> 3) & 0x70u); }

// ---------------------------------------------------------------------------
// FP16 tensor-core GEMM:  C[m,n] = alpha * (A[m,:] . B[n,:]) (+ bias[n])
// A: [M][K] half row-major (lda). B: [N][K] half row-major (ldb).  C = A @ B^T.
// Tiles: BM=128, BN=128, BK=64 halfs (128B rows, SW128). 3-stage cp.async ring.
// 256 threads, 8 warps (2 x 4), warp tile 64x32 -> 4 m-frags x 4 n-frags.
// TRANSC: write C transposed [n][m] half.  OUTF32: write fp32 C.
// ---------------------------------------------------------------------------
#define STAGE_BYTES 32768u       // A 16KB + B 16KB
#define SMEM_NEED   (3 * STAGE_BYTES)

__device__ __forceinline__ void ld_stage_h(uint32_t sbase,
                                           const __half* __restrict__ A,
                                           const __half* __restrict__ B,
                                           int lda, int ldb, int rowBase, int colBase,
                                           int k0, int tid)
{
    // Tile = 128 rows x 128 bytes = 1024 16B chunks; 8 chunks per row.
#pragma unroll
    for (int i = 0; i < 4; i++) {                 // A
        int idx = tid + 256 * i;                  // 0..1023
        int row = idx >> 3;                       // 0..127
        int c8  = idx & 7;                        // 0..7
        uint32_t dst = sbase + SWZ128((uint32_t)(row * 128 + c8 * 16));
        const __half* src = A + (size_t)(rowBase + row) * lda + k0 + c8 * 8;
        CP_ASYNC16(dst, src);
    }
#pragma unroll
    for (int i = 0; i < 4; i++) {                 // B
        int idx = tid + 256 * i;
        int row = idx >> 3;
        int c8  = idx & 7;
        uint32_t dst = sbase + 16384u + SWZ128((uint32_t)(row * 128 + c8 * 16));
        const __half* src = B + (size_t)(colBase + row) * ldb + k0 + c8 * 8;
        CP_ASYNC16(dst, src);
    }
}

template <bool BIAS, bool TRANSC, bool OUTF32>
__global__ __launch_bounds__(256, 2)
void gemm_h(const __half* __restrict__ A, const __half* __restrict__ B,
            const float* __restrict__ bias, void* __restrict__ Cv,
            int K, int lda, int ldb, int ldc, float alpha)
{
    extern __shared__ char smem[];
    const uint32_t sbase = (uint32_t)__cvta_generic_to_shared(smem);

    const int tid  = threadIdx.x;
    const int lane = tid & 31;
    const int warp = tid >> 5;
    const int wm   = warp >> 2;                   // 0..1
    const int wn   = warp & 3;                    // 0..3

    const int rowBase = blockIdx.y * 128;
    const int colBase = blockIdx.x * 128;

    float acc[4][4][4];
#pragma unroll
    for (int mi = 0; mi < 4; mi++)
#pragma unroll
        for (int ni = 0; ni < 4; ni++)
#pragma unroll
            for (int r = 0; r < 4; r++) acc[mi][ni][r] = 0.0f;

    // Per-thread ldmatrix byte-offset bases (pre-swizzle)
    const uint32_t aRowB = (uint32_t)((wm * 64 + (lane & 15)) * 128 + ((lane >> 4) & 1) * 16);
    const uint32_t bRowB = (uint32_t)((wn * 32 + ((lane >> 4) & 1) * 8 + (lane & 7)) * 128
                                      + ((lane >> 3) & 1) * 16);

    // Prologue: stages 0 and 1
    ld_stage_h(sbase + 0 * STAGE_BYTES, A, B, lda, ldb, rowBase, colBase, 0, tid);
    CP_COMMIT();
    ld_stage_h(sbase + 1 * STAGE_BYTES, A, B, lda, ldb, rowBase, colBase, 64, tid);
    CP_COMMIT();

    const int S = K >> 6;                         // K / 64
    for (int s = 0; s < S; s++) {
        if (s == S - 1) { CP_WAIT(0); } else { CP_WAIT(1); }
        __syncthreads();

        if (s + 2 < S) {
            ld_stage_h(sbase + (uint32_t)((s + 2) % 3) * STAGE_BYTES,
                       A, B, lda, ldb, rowBase, colBase, (s + 2) * 64, tid);
            CP_COMMIT();
        }

        const uint32_t aB = sbase + (uint32_t)(s % 3) * STAGE_BYTES;
        const uint32_t bB = aB + 16384u;

#pragma unroll
        for (int ks = 0; ks < 4; ks++) {
            uint32_t af[4][4], bf[4][2];
#pragma unroll
            for (int mi = 0; mi < 4; mi++) {
                uint32_t addr = aB + SWZ128(aRowB + (uint32_t)(mi * 16 * 128) + (uint32_t)(ks * 32));
                LDSM_X4(af[mi][0], af[mi][1], af[mi][2], af[mi][3], addr);
            }
#pragma unroll
            for (int nj = 0; nj < 2; nj++) {
                uint32_t addr = bB + SWZ128(bRowB + (uint32_t)(nj * 16 * 128) + (uint32_t)(ks * 32));
                LDSM_X4(bf[2 * nj][0], bf[2 * nj][1], bf[2 * nj + 1][0], bf[2 * nj + 1][1], addr);
            }
#pragma unroll
            for (int mi = 0; mi < 4; mi++)
#pragma unroll
                for (int ni = 0; ni < 4; ni++)
                    MMA_F16(acc[mi][ni], af[mi], bf[ni]);
        }
        __syncthreads();
    }

    // Epilogue
    const int g  = lane >> 2;
    const int t4 = lane & 3;
#pragma unroll
    for (int mi = 0; mi < 4; mi++) {
#pragma unroll
        for (int ni = 0; ni < 4; ni++) {
            const int row0 = rowBase + wm * 64 + mi * 16 + g;
            const int col  = colBase + wn * 32 + ni * 8 + 2 * t4;
            float b0 = 0.0f, b1 = 0.0f;
            if (BIAS) { b0 = bias[col]; b1 = bias[col + 1]; }
            float c0 = alpha * acc[mi][ni][0] + b0;
            float c1 = alpha * acc[mi][ni][1] + b1;
            float c2 = alpha * acc[mi][ni][2] + b0;
            float c3 = alpha * acc[mi][ni][3] + b1;
            if (OUTF32) {
                float* C = (float*)Cv;
                *reinterpret_cast<float2*>(&C[(size_t)row0 * ldc + col])       = make_float2(c0, c1);
                *reinterpret_cast<float2*>(&C[(size_t)(row0 + 8) * ldc + col]) = make_float2(c2, c3);
            } else if (TRANSC) {
                __half* C = (__half*)Cv;
                C[(size_t)col * ldc + row0]           = __float2half_rn(c0);
                C[(size_t)(col + 1) * ldc + row0]     = __float2half_rn(c1);
                C[(size_t)col * ldc + row0 + 8]       = __float2half_rn(c2);
                C[(size_t)(col + 1) * ldc + row0 + 8] = __float2half_rn(c3);
            } else {
                __half* C = (__half*)Cv;
                *reinterpret_cast<__half2*>(&C[(size_t)row0 * ldc + col]) =
                    __floats2half2_rn(c0, c1);
                *reinterpret_cast<__half2*>(&C[(size_t)(row0 + 8) * ldc + col]) =
                    __floats2half2_rn(c2, c3);
            }
        }
    }
}

// ---------------------------------------------------------------------------
// fp32 -> fp16 convert (grid-stride, float4 -> 4 halfs)
// ---------------------------------------------------------------------------
__global__ __launch_bounds__(256)
void cvt_f2h(const float* __restrict__ in, __half* __restrict__ out, int n4)
{
    int i = blockIdx.x * blockDim.x + threadIdx.x;
    int stride = gridDim.x * blockDim.x;
    for (; i < n4; i += stride) {
        float4 v = reinterpret_cast<const float4*>(in)[i];
        __half2 h0 = __floats2half2_rn(v.x, v.y);
        __half2 h1 = __floats2half2_rn(v.z, v.w);
        reinterpret_cast<__half2*>(out)[2 * i]     = h0;
        reinterpret_cast<__half2*>(out)[2 * i + 1] = h1;
    }
}

// ---------------------------------------------------------------------------
// Row softmax on fp16 S (8192/row), in place. P scaled by 256 (fp16-normal range).
// ---------------------------------------------------------------------------
__global__ __launch_bounds__(256)
void softmax_h(__half* __restrict__ S)
{
    __shared__ float red[256];
    const int row = blockIdx.x;
    const int t = threadIdx.x;
    uint4* p = reinterpret_cast<uint4*>(S + (size_t)row * MKV);   // 8 halfs per uint4

    float v[32];
    float mx = -INFINITY;
#pragma unroll
    for (int i = 0; i < 4; i++) {
        uint4 u = p[t + i * 256];
        const uint32_t w[4] = {u.x, u.y, u.z, u.w};
#pragma unroll
        for (int j = 0; j < 4; j++) {
            float2 f = __half22float2(*reinterpret_cast<const __half2*>(&w[j]));
            v[i * 8 + 2 * j]     = f.x;
            v[i * 8 + 2 * j + 1] = f.y;
            mx = fmaxf(mx, fmaxf(f.x, f.y));
        }
    }
    red[t] = mx; __syncthreads();
    for (int s = 128; s > 0; s >>= 1) {
        if (t < s) red[t] = fmaxf(red[t], red[t + s]);
        __syncthreads();
    }
    mx = red[0]; __syncthreads();

    float sum = 0.0f;
#pragma unroll
    for (int i = 0; i < 32; i++) { v[i] = __expf(v[i] - mx); sum += v[i]; }
    red[t] = sum; __syncthreads();
    for (int s = 128; s > 0; s >>= 1) {
        if (t < s) red[t] += red[t + s];
        __syncthreads();
    }
    const float inv = 256.0f / red[0];   // x256: keep P in fp16-normal range

#pragma unroll
    for (int i = 0; i < 4; i++) {
        uint4 u;
        uint32_t* w = &u.x;
#pragma unroll
        for (int j = 0; j < 4; j++) {
            __half2 h = __floats2half2_rn(v[i * 8 + 2 * j] * inv, v[i * 8 + 2 * j + 1] * inv);
            w[j] = *reinterpret_cast<uint32_t*>(&h);
        }
        p[t + i * 256] = u;
    }
}

// ---------------------------------------------------------------------------
// Launch
// ---------------------------------------------------------------------------
extern "C" void kernel_launch(void* const* d_in, const int* in_sizes, int n_in,
                              void* d_out, int out_size)
{
    const float* query = (const float*)d_in[0];
    const float* key   = (const float*)d_in[1];
    const float* value = (const float*)d_in[2];
    const float* Wq    = (const float*)d_in[3];
    const float* bq    = (const float*)d_in[4];
    const float* Wk    = (const float*)d_in[5];
    const float* bk    = (const float*)d_in[6];
    const float* Wv    = (const float*)d_in[7];
    const float* bv    = (const float*)d_in[8];
    float* out = (float*)d_out;

    __half *qh, *kh, *vh, *Wqh, *Wkh, *Wvh, *Qh, *Kh, *Vth, *Sh;
    cudaGetSymbolAddress((void**)&qh,  g_qh);
    cudaGetSymbolAddress((void**)&kh,  g_kh);
    cudaGetSymbolAddress((void**)&vh,  g_vh);
    cudaGetSymbolAddress((void**)&Wqh, g_Wqh);
    cudaGetSymbolAddress((void**)&Wkh, g_Wkh);
    cudaGetSymbolAddress((void**)&Wvh, g_Wvh);
    cudaGetSymbolAddress((void**)&Qh,  g_Qh);
    cudaGetSymbolAddress((void**)&Kh,  g_Kh);
    cudaGetSymbolAddress((void**)&Vth, g_Vth);
    cudaGetSymbolAddress((void**)&Sh,  g_Sh);

    cudaFuncSetAttribute(gemm_h<true,  false, false>,
                         cudaFuncAttributeMaxDynamicSharedMemorySize, SMEM_NEED);
    cudaFuncSetAttribute(gemm_h<true,  true,  false>,
                         cudaFuncAttributeMaxDynamicSharedMemorySize, SMEM_NEED);
    cudaFuncSetAttribute(gemm_h<false, false, false>,
                         cudaFuncAttributeMaxDynamicSharedMemorySize, SMEM_NEED);
    cudaFuncSetAttribute(gemm_h<false, false, true>,
                         cudaFuncAttributeMaxDynamicSharedMemorySize, SMEM_NEED);

    // 1) fp32 -> fp16 converts
    cvt_f2h<<<2048, 256>>>(query, qh, NQ * DIM / 4);
    cvt_f2h<<<2048, 256>>>(key,   kh, MKV * DIM / 4);
    cvt_f2h<<<2048, 256>>>(value, vh, MKV * DIM / 4);
    cvt_f2h<<<512,  256>>>(Wq, Wqh, DIM * DIM / 4);
    cvt_f2h<<<512,  256>>>(Wk, Wkh, DIM * DIM / 4);
    cvt_f2h<<<512,  256>>>(Wv, Wvh, DIM * DIM / 4);

    // 2) Projections: X @ W^T + b (M=8192, N=1024, K=1024)
    {
        dim3 grid(DIM / 128, NQ / 128);
        gemm_h<true, false, false><<<grid, 256, SMEM_NEED>>>(
            qh, Wqh, bq, Qh, DIM, DIM, DIM, DIM, 1.0f);
        gemm_h<true, false, false><<<grid, 256, SMEM_NEED>>>(
            kh, Wkh, bk, Kh, DIM, DIM, DIM, DIM, 1.0f);
        gemm_h<true, true, false><<<grid, 256, SMEM_NEED>>>(   // V -> transposed [d][m]
            vh, Wvh, bv, Vth, DIM, DIM, DIM, MKV, 1.0f);
    }
    // 3) S = Q K^T / 32 (M=8192, N=8192, K=1024), fp16 logits
    {
        dim3 grid(MKV / 128, NQ / 128);
        gemm_h<false, false, false><<<grid, 256, SMEM_NEED>>>(
            Qh, Kh, nullptr, Sh, DIM, DIM, DIM, MKV, 1.0f / 32.0f);
    }
    // 4) softmax rows (P scaled by 256)
    softmax_h<<<NQ, 256>>>(Sh);
    // 5) out = (P/256) @ V : A=Sh [m][k], B=Vth [n=d][k=m], fp32 out, alpha=1/256
    {
        dim3 grid(DIM / 128, NQ / 128);
        gemm_h<false, false, true><<<grid, 256, SMEM_NEED>>>(
            Sh, Vth, nullptr, out, MKV, MKV, MKV, DIM, 1.0f / 256.0f);
    }
}

// round 7
// speedup vs baseline: 8.5652x; 1.0296x over previous
#include <cuda_runtime.h>
#include <cuda_fp16.h>
#include <math.h>
#include <stdint.h>

#define NQ   8192
#define MKV  8192
#define DIM  1024

// ---------------------------------------------------------------------------
// Scratch (__device__ globals)
// ---------------------------------------------------------------------------
__device__ __half g_qh[(size_t)NQ * DIM];
__device__ __half g_kh[(size_t)MKV * DIM];
__device__ __half g_vh[(size_t)MKV * DIM];
__device__ __half g_Wqh[(size_t)DIM * DIM];
__device__ __half g_Wkh[(size_t)DIM * DIM];
__device__ __half g_Wvh[(size_t)DIM * DIM];
__device__ __half g_Qh[(size_t)NQ * DIM];
__device__ __half g_Kh[(size_t)MKV * DIM];
__device__ __half g_Vth[(size_t)DIM * MKV];         // V^T [d][m]
__device__ __half g_Sh[(size_t)NQ * MKV];           // 128 MB

// ---------------------------------------------------------------------------
// PTX helpers
// ---------------------------------------------------------------------------
#define CP_ASYNC16(dst, src) \
    asm volatile("cp.async.cg.shared.global [%0], [%1], 16;" :: "r"(dst), "l"(src))
#define CP_COMMIT() asm volatile("cp.async.commit_group;")
#define CP_WAIT(n)  asm volatile("cp.async.wait_group %0;" :: "n"(n))

#define LDSM_X4(r0, r1, r2, r3, addr)                                            \
    asm volatile("ldmatrix.sync.aligned.m8n8.x4.shared.b16 {%0,%1,%2,%3}, [%4];" \
                 : "=r"(r0), "=r"(r1), "=r"(r2), "=r"(r3) : "r"(addr))

#define MMA_F16(d, a, b)                                                          \
    asm volatile("mma.sync.aligned.m16n8k16.row.col.f32.f16.f16.f32 "             \
                 "{%0,%1,%2,%3},{%4,%5,%6,%7},{%8,%9},{%0,%1,%2,%3};"             \
                 : "+f"((d)[0]), "+f"((d)[1]), "+f"((d)[2]), "+f"((d)[3])         \
                 : "r"((a)[0]), "r"((a)[1]), "r"((a)[2]), "r"((a)[3]),            \
                   "r"((b)[0]), "r"((b)[1]))

__device__ __forceinline__ uint32_t SWZ128(uint32_t o) { return o ^ ((o >> 3) & 0x70u); }

// ---------------------------------------------------------------------------
// FP16 tensor-core GEMM:  C[m,n] = alpha * (A[m,:] . B[n,:]) (+ bias[n])
// BM=128, BN=256, BK=64 halfs. 3-stage cp.async ring (48 KB/stage).
// 8 warps, 2x4 grid, warp tile 64x64 -> 4 m-frags x 8 n-frags (128 acc regs).
// ---------------------------------------------------------------------------
#define STAGE_A     16384u                 // 128 rows x 128 B
#define STAGE_BYTES 49152u                 // A 16KB + B 32KB
#define SMEM_NEED   (3 * STAGE_BYTES)      // 144 KB

__device__ __forceinline__ void ld_stage_h(uint32_t sbase,
                                           const __half* __restrict__ A,
                                           const __half* __restrict__ B,
                                           int lda, int ldb, int rowBase, int colBase,
                                           int k0, int tid)
{
#pragma unroll
    for (int i = 0; i < 4; i++) {                 // A: 1024 chunks (128 rows x 8)
        int idx = tid + 256 * i;
        int row = idx >> 3;
        int c8  = idx & 7;
        uint32_t dst = sbase + SWZ128((uint32_t)(row * 128 + c8 * 16));
        const __half* src = A + (size_t)(rowBase + row) * lda + k0 + c8 * 8;
        CP_ASYNC16(dst, src);
    }
#pragma unroll
    for (int i = 0; i < 8; i++) {                 // B: 2048 chunks (256 rows x 8)
        int idx = tid + 256 * i;
        int row = idx >> 3;
        int c8  = idx & 7;
        uint32_t dst = sbase + STAGE_A + SWZ128((uint32_t)(row * 128 + c8 * 16));
        const __half* src = B + (size_t)(colBase + row) * ldb + k0 + c8 * 8;
        CP_ASYNC16(dst, src);
    }
}

template <bool BIAS, bool TRANSC, bool OUTF32>
__global__ __launch_bounds__(256, 1)
void gemm_h(const __half* __restrict__ A, const __half* __restrict__ B,
            const float* __restrict__ bias, void* __restrict__ Cv,
            int K, int lda, int ldb, int ldc, float alpha)
{
    extern __shared__ char smem[];
    const uint32_t sbase = (uint32_t)__cvta_generic_to_shared(smem);

    const int tid  = threadIdx.x;
    const int lane = tid & 31;
    const int warp = tid >> 5;
    const int wm   = warp >> 2;                   // 0..1 -> 64-row band
    const int wn   = warp & 3;                    // 0..3 -> 64-col band

    const int rowBase = blockIdx.y * 128;
    const int colBase = blockIdx.x * 256;

    float acc[4][8][4];
#pragma unroll
    for (int mi = 0; mi < 4; mi++)
#pragma unroll
        for (int ni = 0; ni < 8; ni++)
#pragma unroll
            for (int r = 0; r < 4; r++) acc[mi][ni][r] = 0.0f;

    // ldmatrix per-thread base byte offsets (pre-swizzle)
    const uint32_t aRowB = (uint32_t)((wm * 64 + (lane & 15)) * 128 + ((lane >> 4) & 1) * 16);
    const uint32_t bRowB = (uint32_t)((wn * 64 + ((lane >> 4) & 1) * 8 + (lane & 7)) * 128
                                      + ((lane >> 3) & 1) * 16);

    ld_stage_h(sbase + 0 * STAGE_BYTES, A, B, lda, ldb, rowBase, colBase, 0, tid);
    CP_COMMIT();
    ld_stage_h(sbase + 1 * STAGE_BYTES, A, B, lda, ldb, rowBase, colBase, 64, tid);
    CP_COMMIT();

    const int S = K >> 6;
    for (int s = 0; s < S; s++) {
        if (s == S - 1) { CP_WAIT(0); } else { CP_WAIT(1); }
        __syncthreads();

        if (s + 2 < S) {
            ld_stage_h(sbase + (uint32_t)((s + 2) % 3) * STAGE_BYTES,
                       A, B, lda, ldb, rowBase, colBase, (s + 2) * 64, tid);
            CP_COMMIT();
        }

        const uint32_t aB = sbase + (uint32_t)(s % 3) * STAGE_BYTES;
        const uint32_t bB = aB + STAGE_A;

#pragma unroll
        for (int ks = 0; ks < 4; ks++) {
            uint32_t af[4][4], bf[8][2];
#pragma unroll
            for (int mi = 0; mi < 4; mi++) {
                uint32_t addr = aB + SWZ128(aRowB + (uint32_t)(mi * 16 * 128) + (uint32_t)(ks * 32));
                LDSM_X4(af[mi][0], af[mi][1], af[mi][2], af[mi][3], addr);
            }
#pragma unroll
            for (int nj = 0; nj < 4; nj++) {
                uint32_t addr = bB + SWZ128(bRowB + (uint32_t)(nj * 16 * 128) + (uint32_t)(ks * 32));
                LDSM_X4(bf[2 * nj][0], bf[2 * nj][1], bf[2 * nj + 1][0], bf[2 * nj + 1][1], addr);
            }
#pragma unroll
            for (int mi = 0; mi < 4; mi++)
#pragma unroll
                for (int ni = 0; ni < 8; ni++)
                    MMA_F16(acc[mi][ni], af[mi], bf[ni]);
        }
        __syncthreads();
    }

    // Epilogue
    const int g  = lane >> 2;
    const int t4 = lane & 3;
#pragma unroll
    for (int mi = 0; mi < 4; mi++) {
#pragma unroll
        for (int ni = 0; ni < 8; ni++) {
            const int row0 = rowBase + wm * 64 + mi * 16 + g;
            const int col  = colBase + wn * 64 + ni * 8 + 2 * t4;
            float b0 = 0.0f, b1 = 0.0f;
            if (BIAS) { b0 = bias[col]; b1 = bias[col + 1]; }
            float c0 = alpha * acc[mi][ni][0] + b0;
            float c1 = alpha * acc[mi][ni][1] + b1;
            float c2 = alpha * acc[mi][ni][2] + b0;
            float c3 = alpha * acc[mi][ni][3] + b1;
            if (OUTF32) {
                float* C = (float*)Cv;
                *reinterpret_cast<float2*>(&C[(size_t)row0 * ldc + col])       = make_float2(c0, c1);
                *reinterpret_cast<float2*>(&C[(size_t)(row0 + 8) * ldc + col]) = make_float2(c2, c3);
            } else if (TRANSC) {
                __half* C = (__half*)Cv;
                C[(size_t)col * ldc + row0]           = __float2half_rn(c0);
                C[(size_t)(col + 1) * ldc + row0]     = __float2half_rn(c1);
                C[(size_t)col * ldc + row0 + 8]       = __float2half_rn(c2);
                C[(size_t)(col + 1) * ldc + row0 + 8] = __float2half_rn(c3);
            } else {
                __half* C = (__half*)Cv;
                *reinterpret_cast<__half2*>(&C[(size_t)row0 * ldc + col]) =
                    __floats2half2_rn(c0, c1);
                *reinterpret_cast<__half2*>(&C[(size_t)(row0 + 8) * ldc + col]) =
                    __floats2half2_rn(c2, c3);
            }
        }
    }
}

// ---------------------------------------------------------------------------
// fp32 -> fp16 convert
// ---------------------------------------------------------------------------
__global__ __launch_bounds__(256)
void cvt_f2h(const float* __restrict__ in, __half* __restrict__ out, int n4)
{
    int i = blockIdx.x * blockDim.x + threadIdx.x;
    int stride = gridDim.x * blockDim.x;
    for (; i < n4; i += stride) {
        float4 v = reinterpret_cast<const float4*>(in)[i];
        __half2 h0 = __floats2half2_rn(v.x, v.y);
        __half2 h1 = __floats2half2_rn(v.z, v.w);
        reinterpret_cast<__half2*>(out)[2 * i]     = h0;
        reinterpret_cast<__half2*>(out)[2 * i + 1] = h1;
    }
}

// ---------------------------------------------------------------------------
// Row softmax (fp16 in place), P scaled by 256
// ---------------------------------------------------------------------------
__global__ __launch_bounds__(256)
void softmax_h(__half* __restrict__ S)
{
    __shared__ float red[256];
    const int row = blockIdx.x;
    const int t = threadIdx.x;
    uint4* p = reinterpret_cast<uint4*>(S + (size_t)row * MKV);

    float v[32];
    float mx = -INFINITY;
#pragma unroll
    for (int i = 0; i < 4; i++) {
        uint4 u = p[t + i * 256];
        const uint32_t w[4] = {u.x, u.y, u.z, u.w};
#pragma unroll
        for (int j = 0; j < 4; j++) {
            float2 f = __half22float2(*reinterpret_cast<const __half2*>(&w[j]));
            v[i * 8 + 2 * j]     = f.x;
            v[i * 8 + 2 * j + 1] = f.y;
            mx = fmaxf(mx, fmaxf(f.x, f.y));
        }
    }
    red[t] = mx; __syncthreads();
    for (int s = 128; s > 0; s >>= 1) {
        if (t < s) red[t] = fmaxf(red[t], red[t + s]);
        __syncthreads();
    }
    mx = red[0]; __syncthreads();

    float sum = 0.0f;
#pragma unroll
    for (int i = 0; i < 32; i++) { v[i] = __expf(v[i] - mx); sum += v[i]; }
    red[t] = sum; __syncthreads();
    for (int s = 128; s > 0; s >>= 1) {
        if (t < s) red[t] += red[t + s];
        __syncthreads();
    }
    const float inv = 256.0f / red[0];

#pragma unroll
    for (int i = 0; i < 4; i++) {
        uint4 u;
        uint32_t* w = &u.x;
#pragma unroll
        for (int j = 0; j < 4; j++) {
            __half2 h = __floats2half2_rn(v[i * 8 + 2 * j] * inv, v[i * 8 + 2 * j + 1] * inv);
            w[j] = *reinterpret_cast<uint32_t*>(&h);
        }
        p[t + i * 256] = u;
    }
}

// ---------------------------------------------------------------------------
// Launch
// ---------------------------------------------------------------------------
extern "C" void kernel_launch(void* const* d_in, const int* in_sizes, int n_in,
                              void* d_out, int out_size)
{
    const float* query = (const float*)d_in[0];
    const float* key   = (const float*)d_in[1];
    const float* value = (const float*)d_in[2];
    const float* Wq    = (const float*)d_in[3];
    const float* bq    = (const float*)d_in[4];
    const float* Wk    = (const float*)d_in[5];
    const float* bk    = (const float*)d_in[6];
    const float* Wv    = (const float*)d_in[7];
    const float* bv    = (const float*)d_in[8];
    float* out = (float*)d_out;

    __half *qh, *kh, *vh, *Wqh, *Wkh, *Wvh, *Qh, *Kh, *Vth, *Sh;
    cudaGetSymbolAddress((void**)&qh,  g_qh);
    cudaGetSymbolAddress((void**)&kh,  g_kh);
    cudaGetSymbolAddress((void**)&vh,  g_vh);
    cudaGetSymbolAddress((void**)&Wqh, g_Wqh);
    cudaGetSymbolAddress((void**)&Wkh, g_Wkh);
    cudaGetSymbolAddress((void**)&Wvh, g_Wvh);
    cudaGetSymbolAddress((void**)&Qh,  g_Qh);
    cudaGetSymbolAddress((void**)&Kh,  g_Kh);
    cudaGetSymbolAddress((void**)&Vth, g_Vth);
    cudaGetSymbolAddress((void**)&Sh,  g_Sh);

    cudaFuncSetAttribute(gemm_h<true,  false, false>,
                         cudaFuncAttributeMaxDynamicSharedMemorySize, SMEM_NEED);
    cudaFuncSetAttribute(gemm_h<true,  true,  false>,
                         cudaFuncAttributeMaxDynamicSharedMemorySize, SMEM_NEED);
    cudaFuncSetAttribute(gemm_h<false, false, false>,
                         cudaFuncAttributeMaxDynamicSharedMemorySize, SMEM_NEED);
    cudaFuncSetAttribute(gemm_h<false, false, true>,
                         cudaFuncAttributeMaxDynamicSharedMemorySize, SMEM_NEED);

    // 1) fp32 -> fp16 converts
    cvt_f2h<<<2048, 256>>>(query, qh, NQ * DIM / 4);
    cvt_f2h<<<2048, 256>>>(key,   kh, MKV * DIM / 4);
    cvt_f2h<<<2048, 256>>>(value, vh, MKV * DIM / 4);
    cvt_f2h<<<1024, 256>>>(Wq, Wqh, DIM * DIM / 4);
    cvt_f2h<<<1024, 256>>>(Wk, Wkh, DIM * DIM / 4);
    cvt_f2h<<<1024, 256>>>(Wv, Wvh, DIM * DIM / 4);

    // 2) Projections: X @ W^T + b (M=8192, N=1024, K=1024)
    {
        dim3 grid(DIM / 256, NQ / 128);
        gemm_h<true, false, false><<<grid, 256, SMEM_NEED>>>(
            qh, Wqh, bq, Qh, DIM, DIM, DIM, DIM, 1.0f);
        gemm_h<true, false, false><<<grid, 256, SMEM_NEED>>>(
            kh, Wkh, bk, Kh, DIM, DIM, DIM, DIM, 1.0f);
        gemm_h<true, true, false><<<grid, 256, SMEM_NEED>>>(
            vh, Wvh, bv, Vth, DIM, DIM, DIM, MKV, 1.0f);
    }
    // 3) S = Q K^T / 32  (M=8192, N=8192, K=1024)
    {
        dim3 grid(MKV / 256, NQ / 128);
        gemm_h<false, false, false><<<grid, 256, SMEM_NEED>>>(
            Qh, Kh, nullptr, Sh, DIM, DIM, DIM, MKV, 1.0f / 32.0f);
    }
    // 4) softmax (P scaled by 256)
    softmax_h<<<NQ, 256>>>(Sh);
    // 5) out = (P/256) @ V
    {
        dim3 grid(DIM / 256, NQ / 128);
        gemm_h<false, false, true><<<grid, 256, SMEM_NEED>>>(
            Sh, Vth, nullptr, out, MKV, MKV, MKV, DIM, 1.0f / 256.0f);
    }
}

// round 9
// speedup vs baseline: 9.0978x; 1.0622x over previous
#include <cuda_runtime.h>
#include <cuda_fp16.h>
#include <math.h>
#include <stdint.h>

#define NQ   8192
#define MKV  8192
#define DIM  1024

// ---------------------------------------------------------------------------
// Scratch (__device__ globals)
// ---------------------------------------------------------------------------
__device__ __half g_qh[(size_t)NQ * DIM];
__device__ __half g_kh[(size_t)MKV * DIM];
__device__ __half g_vh[(size_t)MKV * DIM];
__device__ __half g_Wqh[(size_t)DIM * DIM];
__device__ __half g_Wkh[(size_t)DIM * DIM];
__device__ __half g_Wvh[(size_t)DIM * DIM];
__device__ __half g_Qh[(size_t)NQ * DIM];
__device__ __half g_Kh[(size_t)MKV * DIM];
__device__ __half g_Vth[(size_t)DIM * MKV];         // V^T [d][m]
__device__ __half g_Sh[(size_t)NQ * MKV];           // 128 MB

// ---------------------------------------------------------------------------
// PTX helpers
// ---------------------------------------------------------------------------
#define CP_ASYNC16(dst, src) \
    asm volatile("cp.async.cg.shared.global [%0], [%1], 16;" :: "r"(dst), "l"(src))
#define CP_COMMIT() asm volatile("cp.async.commit_group;")
#define CP_WAIT(n)  asm volatile("cp.async.wait_group %0;" :: "n"(n))

#define LDSM_X4(r0, r1, r2, r3, addr)                                            \
    asm volatile("ldmatrix.sync.aligned.m8n8.x4.shared.b16 {%0,%1,%2,%3}, [%4];" \
                 : "=r"(r0), "=r"(r1), "=r"(r2), "=r"(r3) : "r"(addr))

#define MMA_F16(d, a, b)                                                          \
    asm volatile("mma.sync.aligned.m16n8k16.row.col.f32.f16.f16.f32 "             \
                 "{%0,%1,%2,%3},{%4,%5,%6,%7},{%8,%9},{%0,%1,%2,%3};"             \
                 : "+f"((d)[0]), "+f"((d)[1]), "+f"((d)[2]), "+f"((d)[3])         \
                 : "r"((a)[0]), "r"((a)[1]), "r"((a)[2]), "r"((a)[3]),            \
                   "r"((b)[0]), "r"((b)[1]))

__device__ __forceinline__ uint32_t SWZ128(uint32_t o) { return o ^ ((o >> 3) & 0x70u); }

// ---------------------------------------------------------------------------
// FP16 tensor-core GEMM:  C[m,n] = alpha * (A[m,:] . B[n,:]) (+ bias[n])
// BM=128, BN=128, BK=64 halfs. 3-stage cp.async ring (32 KB/stage, 96 KB).
// 128 threads, 4 warps (2x2), warp tile 64x64 -> 4 m-frags x 8 n-frags.
// 2 CTAs/SM for cross-CTA latency hiding.
// ---------------------------------------------------------------------------
#define STAGE_A     16384u                 // 128 rows x 128 B
#define STAGE_BYTES 32768u                 // A 16KB + B 16KB
#define SMEM_NEED   (3 * STAGE_BYTES)      // 96 KB

__device__ __forceinline__ void ld_stage_h(uint32_t sbase,
                                           const __half* __restrict__ A,
                                           const __half* __restrict__ B,
                                           int lda, int ldb, int rowBase, int colBase,
                                           int k0, int tid)
{
#pragma unroll
    for (int i = 0; i < 8; i++) {                 // A: 1024 chunks (128 rows x 8)
        int idx = tid + 128 * i;
        int row = idx >> 3;
        int c8  = idx & 7;
        uint32_t dst = sbase + SWZ128((uint32_t)(row * 128 + c8 * 16));
        const __half* src = A + (size_t)(rowBase + row) * lda + k0 + c8 * 8;
        CP_ASYNC16(dst, src);
    }
#pragma unroll
    for (int i = 0; i < 8; i++) {                 // B: 1024 chunks (128 rows x 8)
        int idx = tid + 128 * i;
        int row = idx >> 3;
        int c8  = idx & 7;
        uint32_t dst = sbase + STAGE_A + SWZ128((uint32_t)(row * 128 + c8 * 16));
        const __half* src = B + (size_t)(colBase + row) * ldb + k0 + c8 * 8;
        CP_ASYNC16(dst, src);
    }
}

template <bool BIAS, bool TRANSC, bool OUTF32>
__global__ __launch_bounds__(128, 2)
void gemm_h(const __half* __restrict__ A, const __half* __restrict__ B,
            const float* __restrict__ bias, void* __restrict__ Cv,
            int K, int lda, int ldb, int ldc, float alpha)
{
    extern __shared__ char smem[];
    const uint32_t sbase = (uint32_t)__cvta_generic_to_shared(smem);

    const int tid  = threadIdx.x;
    const int lane = tid & 31;
    const int warp = tid >> 5;
    const int wm   = warp >> 1;                   // 0..1 -> 64-row band
    const int wn   = warp & 1;                    // 0..1 -> 64-col band

    const int rowBase = blockIdx.y * 128;
    const int colBase = blockIdx.x * 128;

    float acc[4][8][4];
#pragma unroll
    for (int mi = 0; mi < 4; mi++)
#pragma unroll
        for (int ni = 0; ni < 8; ni++)
#pragma unroll
            for (int r = 0; r < 4; r++) acc[mi][ni][r] = 0.0f;

    // ldmatrix per-thread base byte offsets (pre-swizzle)
    const uint32_t aRowB = (uint32_t)((wm * 64 + (lane & 15)) * 128 + ((lane >> 4) & 1) * 16);
    const uint32_t bRowB = (uint32_t)((wn * 64 + ((lane >> 4) & 1) * 8 + (lane & 7)) * 128
                                      + ((lane >> 3) & 1) * 16);

    ld_stage_h(sbase + 0 * STAGE_BYTES, A, B, lda, ldb, rowBase, colBase, 0, tid);
    CP_COMMIT();
    ld_stage_h(sbase + 1 * STAGE_BYTES, A, B, lda, ldb, rowBase, colBase, 64, tid);
    CP_COMMIT();

    const int S = K >> 6;
    for (int s = 0; s < S; s++) {
        if (s == S - 1) { CP_WAIT(0); } else { CP_WAIT(1); }
        __syncthreads();

        if (s + 2 < S) {
            ld_stage_h(sbase + (uint32_t)((s + 2) % 3) * STAGE_BYTES,
                       A, B, lda, ldb, rowBase, colBase, (s + 2) * 64, tid);
            CP_COMMIT();
        }

        const uint32_t aB = sbase + (uint32_t)(s % 3) * STAGE_BYTES;
        const uint32_t bB = aB + STAGE_A;

#pragma unroll
        for (int ks = 0; ks < 4; ks++) {
            uint32_t af[4][4], bf[8][2];
#pragma unroll
            for (int mi = 0; mi < 4; mi++) {
                uint32_t addr = aB + SWZ128(aRowB + (uint32_t)(mi * 16 * 128) + (uint32_t)(ks * 32));
                LDSM_X4(af[mi][0], af[mi][1], af[mi][2], af[mi][3], addr);
            }
#pragma unroll
            for (int nj = 0; nj < 4; nj++) {
                uint32_t addr = bB + SWZ128(bRowB + (uint32_t)(nj * 16 * 128) + (uint32_t)(ks * 32));
                LDSM_X4(bf[2 * nj][0], bf[2 * nj][1], bf[2 * nj + 1][0], bf[2 * nj + 1][1], addr);
            }
#pragma unroll
            for (int mi = 0; mi < 4; mi++)
#pragma unroll
                for (int ni = 0; ni < 8; ni++)
                    MMA_F16(acc[mi][ni], af[mi], bf[ni]);
        }
        __syncthreads();
    }

    // Epilogue
    const int g  = lane >> 2;
    const int t4 = lane & 3;
#pragma unroll
    for (int mi = 0; mi < 4; mi++) {
#pragma unroll
        for (int ni = 0; ni < 8; ni++) {
            const int row0 = rowBase + wm * 64 + mi * 16 + g;
            const int col  = colBase + wn * 64 + ni * 8 + 2 * t4;
            float b0 = 0.0f, b1 = 0.0f;
            if (BIAS) { b0 = bias[col]; b1 = bias[col + 1]; }
            float c0 = alpha * acc[mi][ni][0] + b0;
            float c1 = alpha * acc[mi][ni][1] + b1;
            float c2 = alpha * acc[mi][ni][2] + b0;
            float c3 = alpha * acc[mi][ni][3] + b1;
            if (OUTF32) {
                float* C = (float*)Cv;
                *reinterpret_cast<float2*>(&C[(size_t)row0 * ldc + col])       = make_float2(c0, c1);
                *reinterpret_cast<float2*>(&C[(size_t)(row0 + 8) * ldc + col]) = make_float2(c2, c3);
            } else if (TRANSC) {
                __half* C = (__half*)Cv;
                C[(size_t)col * ldc + row0]           = __float2half_rn(c0);
                C[(size_t)(col + 1) * ldc + row0]     = __float2half_rn(c1);
                C[(size_t)col * ldc + row0 + 8]       = __float2half_rn(c2);
                C[(size_t)(col + 1) * ldc + row0 + 8] = __float2half_rn(c3);
            } else {
                __half* C = (__half*)Cv;
                *reinterpret_cast<__half2*>(&C[(size_t)row0 * ldc + col]) =
                    __floats2half2_rn(c0, c1);
                *reinterpret_cast<__half2*>(&C[(size_t)(row0 + 8) * ldc + col]) =
                    __floats2half2_rn(c2, c3);
            }
        }
    }
}

// ---------------------------------------------------------------------------
// fp32 -> fp16 convert
// ---------------------------------------------------------------------------
__global__ __launch_bounds__(256)
void cvt_f2h(const float* __restrict__ in, __half* __restrict__ out, int n4)
{
    int i = blockIdx.x * blockDim.x + threadIdx.x;
    int stride = gridDim.x * blockDim.x;
    for (; i < n4; i += stride) {
        float4 v = reinterpret_cast<const float4*>(in)[i];
        __half2 h0 = __floats2half2_rn(v.x, v.y);
        __half2 h1 = __floats2half2_rn(v.z, v.w);
        reinterpret_cast<__half2*>(out)[2 * i]     = h0;
        reinterpret_cast<__half2*>(out)[2 * i + 1] = h1;
    }
}

// ---------------------------------------------------------------------------
// Row softmax (fp16 in place), P scaled by 256
// ---------------------------------------------------------------------------
__global__ __launch_bounds__(256)
void softmax_h(__half* __restrict__ S)
{
    __shared__ float red[256];
    const int row = blockIdx.x;
    const int t = threadIdx.x;
    uint4* p = reinterpret_cast<uint4*>(S + (size_t)row * MKV);

    float v[32];
    float mx = -INFINITY;
#pragma unroll
    for (int i = 0; i < 4; i++) {
        uint4 u = p[t + i * 256];
        const uint32_t w[4] = {u.x, u.y, u.z, u.w};
#pragma unroll
        for (int j = 0; j < 4; j++) {
            float2 f = __half22float2(*reinterpret_cast<const __half2*>(&w[j]));
            v[i * 8 + 2 * j]     = f.x;
            v[i * 8 + 2 * j + 1] = f.y;
            mx = fmaxf(mx, fmaxf(f.x, f.y));
        }
    }
    red[t] = mx; __syncthreads();
    for (int s = 128; s > 0; s >>= 1) {
        if (t < s) red[t] = fmaxf(red[t], red[t + s]);
        __syncthreads();
    }
    mx = red[0]; __syncthreads();

    float sum = 0.0f;
#pragma unroll
    for (int i = 0; i < 32; i++) { v[i] = __expf(v[i] - mx); sum += v[i]; }
    red[t] = sum; __syncthreads();
    for (int s = 128; s > 0; s >>= 1) {
        if (t < s) red[t] += red[t + s];
        __syncthreads();
    }
    const float inv = 256.0f / red[0];

#pragma unroll
    for (int i = 0; i < 4; i++) {
        uint4 u;
        uint32_t* w = &u.x;
#pragma unroll
        for (int j = 0; j < 4; j++) {
            __half2 h = __floats2half2_rn(v[i * 8 + 2 * j] * inv, v[i * 8 + 2 * j + 1] * inv);
            w[j] = *reinterpret_cast<uint32_t*>(&h);
        }
        p[t + i * 256] = u;
    }
}

// ---------------------------------------------------------------------------
// Launch
// ---------------------------------------------------------------------------
extern "C" void kernel_launch(void* const* d_in, const int* in_sizes, int n_in,
                              void* d_out, int out_size)
{
    const float* query = (const float*)d_in[0];
    const float* key   = (const float*)d_in[1];
    const float* value = (const float*)d_in[2];
    const float* Wq    = (const float*)d_in[3];
    const float* bq    = (const float*)d_in[4];
    const float* Wk    = (const float*)d_in[5];
    const float* bk    = (const float*)d_in[6];
    const float* Wv    = (const float*)d_in[7];
    const float* bv    = (const float*)d_in[8];
    float* out = (float*)d_out;

    __half *qh, *kh, *vh, *Wqh, *Wkh, *Wvh, *Qh, *Kh, *Vth, *Sh;
    cudaGetSymbolAddress((void**)&qh,  g_qh);
    cudaGetSymbolAddress((void**)&kh,  g_kh);
    cudaGetSymbolAddress((void**)&vh,  g_vh);
    cudaGetSymbolAddress((void**)&Wqh, g_Wqh);
    cudaGetSymbolAddress((void**)&Wkh, g_Wkh);
    cudaGetSymbolAddress((void**)&Wvh, g_Wvh);
    cudaGetSymbolAddress((void**)&Qh,  g_Qh);
    cudaGetSymbolAddress((void**)&Kh,  g_Kh);
    cudaGetSymbolAddress((void**)&Vth, g_Vth);
    cudaGetSymbolAddress((void**)&Sh,  g_Sh);

    cudaFuncSetAttribute(gemm_h<true,  false, false>,
                         cudaFuncAttributeMaxDynamicSharedMemorySize, SMEM_NEED);
    cudaFuncSetAttribute(gemm_h<true,  true,  false>,
                         cudaFuncAttributeMaxDynamicSharedMemorySize, SMEM_NEED);
    cudaFuncSetAttribute(gemm_h<false, false, false>,
                         cudaFuncAttributeMaxDynamicSharedMemorySize, SMEM_NEED);
    cudaFuncSetAttribute(gemm_h<false, false, true>,
                         cudaFuncAttributeMaxDynamicSharedMemorySize, SMEM_NEED);

    // 1) fp32 -> fp16 converts
    cvt_f2h<<<2048, 256>>>(query, qh, NQ * DIM / 4);
    cvt_f2h<<<2048, 256>>>(key,   kh, MKV * DIM / 4);
    cvt_f2h<<<2048, 256>>>(value, vh, MKV * DIM / 4);
    cvt_f2h<<<1024, 256>>>(Wq, Wqh, DIM * DIM / 4);
    cvt_f2h<<<1024, 256>>>(Wk, Wkh, DIM * DIM / 4);
    cvt_f2h<<<1024, 256>>>(Wv, Wvh, DIM * DIM / 4);

    // 2) Projections: X @ W^T + b (M=8192, N=1024, K=1024)
    {
        dim3 grid(DIM / 128, NQ / 128);
        gemm_h<true, false, false><<<grid, 128, SMEM_NEED>>>(
            qh, Wqh, bq, Qh, DIM, DIM, DIM, DIM, 1.0f);
        gemm_h<true, false, false><<<grid, 128, SMEM_NEED>>>(
            kh, Wkh, bk, Kh, DIM, DIM, DIM, DIM, 1.0f);
        gemm_h<true, true, false><<<grid, 128, SMEM_NEED>>>(
            vh, Wvh, bv, Vth, DIM, DIM, DIM, MKV, 1.0f);
    }
    // 3) S = Q K^T / 32  (M=8192, N=8192, K=1024)
    {
        dim3 grid(MKV / 128, NQ / 128);
        gemm_h<false, false, false><<<grid, 128, SMEM_NEED>>>(
            Qh, Kh, nullptr, Sh, DIM, DIM, DIM, MKV, 1.0f / 32.0f);
    }
    // 4) softmax (P scaled by 256)
    softmax_h<<<NQ, 256>>>(Sh);
    // 5) out = (P/256) @ V
    {
        dim3 grid(DIM / 128, NQ / 128);
        gemm_h<false, false, true><<<grid, 128, SMEM_NEED>>>(
            Sh, Vth, nullptr, out, MKV, MKV, MKV, DIM, 1.0f / 256.0f);
    }
}

// round 11
// speedup vs baseline: 9.2600x; 1.0178x over previous
#include <cuda_runtime.h>
#include <cuda_fp16.h>
#include <math.h>
#include <stdint.h>

#define NQ   8192
#define MKV  8192
#define DIM  1024

// ---------------------------------------------------------------------------
// Scratch (__device__ globals)
// ---------------------------------------------------------------------------
__device__ __half g_qh[(size_t)NQ * DIM];
__device__ __half g_kh[(size_t)MKV * DIM];
__device__ __half g_vh[(size_t)MKV * DIM];
__device__ __half g_Wqh[(size_t)DIM * DIM];
__device__ __half g_Wkh[(size_t)DIM * DIM];
__device__ __half g_Wvh[(size_t)DIM * DIM];
__device__ __half g_Qh[(size_t)NQ * DIM];
__device__ __half g_Kh[(size_t)MKV * DIM];
__device__ __half g_Vth[(size_t)DIM * MKV];         // V^T [d][m]
__device__ __half g_Sh[(size_t)NQ * MKV];           // 128 MB

// ---------------------------------------------------------------------------
// PTX helpers
// ---------------------------------------------------------------------------
#define CP_ASYNC16(dst, src) \
    asm volatile("cp.async.cg.shared.global [%0], [%1], 16;" :: "r"(dst), "l"(src))
#define CP_COMMIT() asm volatile("cp.async.commit_group;")
#define CP_WAIT(n)  asm volatile("cp.async.wait_group %0;" :: "n"(n))

#define LDSM_X4(r0, r1, r2, r3, addr)                                            \
    asm volatile("ldmatrix.sync.aligned.m8n8.x4.shared.b16 {%0,%1,%2,%3}, [%4];" \
                 : "=r"(r0), "=r"(r1), "=r"(r2), "=r"(r3) : "r"(addr))

#define MMA_F16(d, a, b)                                                          \
    asm volatile("mma.sync.aligned.m16n8k16.row.col.f32.f16.f16.f32 "             \
                 "{%0,%1,%2,%3},{%4,%5,%6,%7},{%8,%9},{%0,%1,%2,%3};"             \
                 : "+f"((d)[0]), "+f"((d)[1]), "+f"((d)[2]), "+f"((d)[3])         \
                 : "r"((a)[0]), "r"((a)[1]), "r"((a)[2]), "r"((a)[3]),            \
                   "r"((b)[0]), "r"((b)[1]))

__device__ __forceinline__ uint32_t SWZ128(uint32_t o) { return o ^ ((o >> 3) & 0x70u); }

// ---------------------------------------------------------------------------
// FP16 tensor-core GEMM: C[m,n] = alpha * (A[m,:] . B[n,:]) (+ bias[n])
// BM=128, BN=128, BK=64. 3-stage cp.async ring, 128 threads (4 warps, 2x2),
// warp tile 64x64, fragment double-buffering across ks, 2 CTAs/SM.
// ---------------------------------------------------------------------------
#define STAGE_A     16384u
#define STAGE_BYTES 32768u
#define SMEM_NEED   (3 * STAGE_BYTES)      // 96 KB

__device__ __forceinline__ void ld_stage_h(uint32_t sbase,
                                           const __half* __restrict__ A,
                                           const __half* __restrict__ B,
                                           int lda, int ldb, int rowBase, int colBase,
                                           int k0, int tid)
{
#pragma unroll
    for (int i = 0; i < 8; i++) {                 // A: 1024 chunks (128 rows x 8)
        int idx = tid + 128 * i;
        int row = idx >> 3;
        int c8  = idx & 7;
        uint32_t dst = sbase + SWZ128((uint32_t)(row * 128 + c8 * 16));
        const __half* src = A + (size_t)(rowBase + row) * lda + k0 + c8 * 8;
        CP_ASYNC16(dst, src);
    }
#pragma unroll
    for (int i = 0; i < 8; i++) {                 // B
        int idx = tid + 128 * i;
        int row = idx >> 3;
        int c8  = idx & 7;
        uint32_t dst = sbase + STAGE_A + SWZ128((uint32_t)(row * 128 + c8 * 16));
        const __half* src = B + (size_t)(colBase + row) * ldb + k0 + c8 * 8;
        CP_ASYNC16(dst, src);
    }
}

template <bool BIAS, bool TRANSC, bool OUTF32>
__global__ __launch_bounds__(128, 2)
void gemm_h(const __half* __restrict__ A, const __half* __restrict__ B,
            const float* __restrict__ bias, void* __restrict__ Cv,
            int K, int lda, int ldb, int ldc, float alpha)
{
    extern __shared__ char smem[];
    const uint32_t sbase = (uint32_t)__cvta_generic_to_shared(smem);

    const int tid  = threadIdx.x;
    const int lane = tid & 31;
    const int warp = tid >> 5;
    const int wm   = warp >> 1;
    const int wn   = warp & 1;

    const int rowBase = blockIdx.y * 128;
    const int colBase = blockIdx.x * 128;

    float acc[4][8][4];
#pragma unroll
    for (int mi = 0; mi < 4; mi++)
#pragma unroll
        for (int ni = 0; ni < 8; ni++)
#pragma unroll
            for (int r = 0; r < 4; r++) acc[mi][ni][r] = 0.0f;

    const uint32_t aRowB = (uint32_t)((wm * 64 + (lane & 15)) * 128 + ((lane >> 4) & 1) * 16);
    const uint32_t bRowB = (uint32_t)((wn * 64 + ((lane >> 4) & 1) * 8 + (lane & 7)) * 128
                                      + ((lane >> 3) & 1) * 16);

    ld_stage_h(sbase + 0 * STAGE_BYTES, A, B, lda, ldb, rowBase, colBase, 0, tid);
    CP_COMMIT();
    ld_stage_h(sbase + 1 * STAGE_BYTES, A, B, lda, ldb, rowBase, colBase, 64, tid);
    CP_COMMIT();

    const int S = K >> 6;
    for (int s = 0; s < S; s++) {
        // Issue the s+2 load FIRST (its target buffer was consumed in iter s-1),
        // then wait for stage s with up to 2 groups still pending.
        if (s + 2 < S) {
            ld_stage_h(sbase + (uint32_t)((s + 2) % 3) * STAGE_BYTES,
                       A, B, lda, ldb, rowBase, colBase, (s + 2) * 64, tid);
            CP_COMMIT();
            CP_WAIT(2);
        } else {
            CP_WAIT(0);
        }
        __syncthreads();

        const uint32_t aB = sbase + (uint32_t)(s % 3) * STAGE_BYTES;
        const uint32_t bB = aB + STAGE_A;

        // Fragment double-buffer across ks
        uint32_t af[2][4][4], bf[2][8][2];
        {
#pragma unroll
            for (int mi = 0; mi < 4; mi++) {
                uint32_t addr = aB + SWZ128(aRowB + (uint32_t)(mi * 16 * 128));
                LDSM_X4(af[0][mi][0], af[0][mi][1], af[0][mi][2], af[0][mi][3], addr);
            }
#pragma unroll
            for (int nj = 0; nj < 4; nj++) {
                uint32_t addr = bB + SWZ128(bRowB + (uint32_t)(nj * 16 * 128));
                LDSM_X4(bf[0][2*nj][0], bf[0][2*nj][1], bf[0][2*nj+1][0], bf[0][2*nj+1][1], addr);
            }
        }
#pragma unroll
        for (int ks = 0; ks < 4; ks++) {
            const int cur = ks & 1;
            const int nxt = cur ^ 1;
            if (ks < 3) {
#pragma unroll
                for (int mi = 0; mi < 4; mi++) {
                    uint32_t addr = aB + SWZ128(aRowB + (uint32_t)(mi * 16 * 128)
                                                + (uint32_t)((ks + 1) * 32));
                    LDSM_X4(af[nxt][mi][0], af[nxt][mi][1], af[nxt][mi][2], af[nxt][mi][3], addr);
                }
#pragma unroll
                for (int nj = 0; nj < 4; nj++) {
                    uint32_t addr = bB + SWZ128(bRowB + (uint32_t)(nj * 16 * 128)
                                                + (uint32_t)((ks + 1) * 32));
                    LDSM_X4(bf[nxt][2*nj][0], bf[nxt][2*nj][1],
                            bf[nxt][2*nj+1][0], bf[nxt][2*nj+1][1], addr);
                }
            }
#pragma unroll
            for (int mi = 0; mi < 4; mi++)
#pragma unroll
                for (int ni = 0; ni < 8; ni++)
                    MMA_F16(acc[mi][ni], af[cur][mi], bf[cur][ni]);
        }
        __syncthreads();
    }

    // Epilogue
    const int g  = lane >> 2;
    const int t4 = lane & 3;
#pragma unroll
    for (int mi = 0; mi < 4; mi++) {
#pragma unroll
        for (int ni = 0; ni < 8; ni++) {
            const int row0 = rowBase + wm * 64 + mi * 16 + g;
            const int col  = colBase + wn * 64 + ni * 8 + 2 * t4;
            float b0 = 0.0f, b1 = 0.0f;
            if (BIAS) { b0 = bias[col]; b1 = bias[col + 1]; }
            float c0 = alpha * acc[mi][ni][0] + b0;
            float c1 = alpha * acc[mi][ni][1] + b1;
            float c2 = alpha * acc[mi][ni][2] + b0;
            float c3 = alpha * acc[mi][ni][3] + b1;
            if (OUTF32) {
                float* C = (float*)Cv;
                *reinterpret_cast<float2*>(&C[(size_t)row0 * ldc + col])       = make_float2(c0, c1);
                *reinterpret_cast<float2*>(&C[(size_t)(row0 + 8) * ldc + col]) = make_float2(c2, c3);
            } else if (TRANSC) {
                __half* C = (__half*)Cv;
                C[(size_t)col * ldc + row0]           = __float2half_rn(c0);
                C[(size_t)(col + 1) * ldc + row0]     = __float2half_rn(c1);
                C[(size_t)col * ldc + row0 + 8]       = __float2half_rn(c2);
                C[(size_t)(col + 1) * ldc + row0 + 8] = __float2half_rn(c3);
            } else {
                __half* C = (__half*)Cv;
                *reinterpret_cast<__half2*>(&C[(size_t)row0 * ldc + col]) =
                    __floats2half2_rn(c0, c1);
                *reinterpret_cast<__half2*>(&C[(size_t)(row0 + 8) * ldc + col]) =
                    __floats2half2_rn(c2, c3);
            }
        }
    }
}

// ---------------------------------------------------------------------------
// Single fused fp32 -> fp16 convert over all six tensors
// Segments (in float4 units): q 2M | k 2M | v 2M | Wq 256K | Wk 256K | Wv 256K
// ---------------------------------------------------------------------------
#define SEG_BIG  (NQ * DIM / 4)            // 2,097,152 float4
#define SEG_W    (DIM * DIM / 4)           // 262,144 float4
#define SEG_TOT  (3 * SEG_BIG + 3 * SEG_W)

__global__ __launch_bounds__(256)
void cvt_all(const float* __restrict__ q, const float* __restrict__ k,
             const float* __restrict__ v, const float* __restrict__ wq,
             const float* __restrict__ wk, const float* __restrict__ wv,
             __half* __restrict__ qh, __half* __restrict__ kh,
             __half* __restrict__ vh, __half* __restrict__ wqh,
             __half* __restrict__ wkh, __half* __restrict__ wvh)
{
    int i = blockIdx.x * blockDim.x + threadIdx.x;
    const int stride = gridDim.x * blockDim.x;
    for (; i < SEG_TOT; i += stride) {
        const float* src;
        __half* dst;
        int off = i;
        if (off < 3 * SEG_BIG) {
            int seg = off / SEG_BIG;  off -= seg * SEG_BIG;
            src = (seg == 0) ? q : (seg == 1) ? k : v;
            dst = (seg == 0) ? qh : (seg == 1) ? kh : vh;
        } else {
            off -= 3 * SEG_BIG;
            int seg = off / SEG_W;    off -= seg * SEG_W;
            src = (seg == 0) ? wq : (seg == 1) ? wk : wv;
            dst = (seg == 0) ? wqh : (seg == 1) ? wkh : wvh;
        }
        float4 f = reinterpret_cast<const float4*>(src)[off];
        reinterpret_cast<__half2*>(dst)[2 * off]     = __floats2half2_rn(f.x, f.y);
        reinterpret_cast<__half2*>(dst)[2 * off + 1] = __floats2half2_rn(f.z, f.w);
    }
}

// ---------------------------------------------------------------------------
// Row softmax (fp16 in place), P scaled by 256
// ---------------------------------------------------------------------------
__global__ __launch_bounds__(256)
void softmax_h(__half* __restrict__ S)
{
    __shared__ float red[256];
    const int row = blockIdx.x;
    const int t = threadIdx.x;
    uint4* p = reinterpret_cast<uint4*>(S + (size_t)row * MKV);

    float v[32];
    float mx = -INFINITY;
#pragma unroll
    for (int i = 0; i < 4; i++) {
        uint4 u = p[t + i * 256];
        const uint32_t w[4] = {u.x, u.y, u.z, u.w};
#pragma unroll
        for (int j = 0; j < 4; j++) {
            float2 f = __half22float2(*reinterpret_cast<const __half2*>(&w[j]));
            v[i * 8 + 2 * j]     = f.x;
            v[i * 8 + 2 * j + 1] = f.y;
            mx = fmaxf(mx, fmaxf(f.x, f.y));
        }
    }
    red[t] = mx; __syncthreads();
    for (int s = 128; s > 0; s >>= 1) {
        if (t < s) red[t] = fmaxf(red[t], red[t + s]);
        __syncthreads();
    }
    mx = red[0]; __syncthreads();

    float sum = 0.0f;
#pragma unroll
    for (int i = 0; i < 32; i++) { v[i] = __expf(v[i] - mx); sum += v[i]; }
    red[t] = sum; __syncthreads();
    for (int s = 128; s > 0; s >>= 1) {
        if (t < s) red[t] += red[t + s];
        __syncthreads();
    }
    const float inv = 256.0f / red[0];

#pragma unroll
    for (int i = 0; i < 4; i++) {
        uint4 u;
        uint32_t* w = &u.x;
#pragma unroll
        for (int j = 0; j < 4; j++) {
            __half2 h = __floats2half2_rn(v[i * 8 + 2 * j] * inv, v[i * 8 + 2 * j + 1] * inv);
            w[j] = *reinterpret_cast<uint32_t*>(&h);
        }
        p[t + i * 256] = u;
    }
}

// ---------------------------------------------------------------------------
// Launch
// ---------------------------------------------------------------------------
extern "C" void kernel_launch(void* const* d_in, const int* in_sizes, int n_in,
                              void* d_out, int out_size)
{
    const float* query = (const float*)d_in[0];
    const float* key   = (const float*)d_in[1];
    const float* value = (const float*)d_in[2];
    const float* Wq    = (const float*)d_in[3];
    const float* bq    = (const float*)d_in[4];
    const float* Wk    = (const float*)d_in[5];
    const float* bk    = (const float*)d_in[6];
    const float* Wv    = (const float*)d_in[7];
    const float* bv    = (const float*)d_in[8];
    float* out = (float*)d_out;

    __half *qh, *kh, *vh, *Wqh, *Wkh, *Wvh, *Qh, *Kh, *Vth, *Sh;
    cudaGetSymbolAddress((void**)&qh,  g_qh);
    cudaGetSymbolAddress((void**)&kh,  g_kh);
    cudaGetSymbolAddress((void**)&vh,  g_vh);
    cudaGetSymbolAddress((void**)&Wqh, g_Wqh);
    cudaGetSymbolAddress((void**)&Wkh, g_Wkh);
    cudaGetSymbolAddress((void**)&Wvh, g_Wvh);
    cudaGetSymbolAddress((void**)&Qh,  g_Qh);
    cudaGetSymbolAddress((void**)&Kh,  g_Kh);
    cudaGetSymbolAddress((void**)&Vth, g_Vth);
    cudaGetSymbolAddress((void**)&Sh,  g_Sh);

    cudaFuncSetAttribute(gemm_h<true,  false, false>,
                         cudaFuncAttributeMaxDynamicSharedMemorySize, SMEM_NEED);
    cudaFuncSetAttribute(gemm_h<true,  true,  false>,
                         cudaFuncAttributeMaxDynamicSharedMemorySize, SMEM_NEED);
    cudaFuncSetAttribute(gemm_h<false, false, false>,
                         cudaFuncAttributeMaxDynamicSharedMemorySize, SMEM_NEED);
    cudaFuncSetAttribute(gemm_h<false, false, true>,
                         cudaFuncAttributeMaxDynamicSharedMemorySize, SMEM_NEED);

    // 1) one fused fp32->fp16 convert
    cvt_all<<<4096, 256>>>(query, key, value, Wq, Wk, Wv,
                           qh, kh, vh, Wqh, Wkh, Wvh);

    // 2) Projections: X @ W^T + b (M=8192, N=1024, K=1024)
    {
        dim3 grid(DIM / 128, NQ / 128);
        gemm_h<true, false, false><<<grid, 128, SMEM_NEED>>>(
            qh, Wqh, bq, Qh, DIM, DIM, DIM, DIM, 1.0f);
        gemm_h<true, false, false><<<grid, 128, SMEM_NEED>>>(
            kh, Wkh, bk, Kh, DIM, DIM, DIM, DIM, 1.0f);
        gemm_h<true, true, false><<<grid, 128, SMEM_NEED>>>(
            vh, Wvh, bv, Vth, DIM, DIM, DIM, MKV, 1.0f);
    }
    // 3) S = Q K^T / 32  (M=8192, N=8192, K=1024)
    {
        dim3 grid(MKV / 128, NQ / 128);
        gemm_h<false, false, false><<<grid, 128, SMEM_NEED>>>(
            Qh, Kh, nullptr, Sh, DIM, DIM, DIM, MKV, 1.0f / 32.0f);
    }
    // 4) softmax (P scaled by 256)
    softmax_h<<<NQ, 256>>>(Sh);
    // 5) out = (P/256) @ V
    {
        dim3 grid(DIM / 128, NQ / 128);
        gemm_h<false, false, true><<<grid, 128, SMEM_NEED>>>(
            Sh, Vth, nullptr, out, MKV, MKV, MKV, DIM, 1.0f / 256.0f);
    }
}